// round 2
// baseline (speedup 1.0000x reference)
#include <cuda_runtime.h>
#include <math.h>

#define BB   2
#define HH   16
#define SSEQ 2048
#define DH   64
#define EMB  1024
#define MTOT (BB * SSEQ)   // 4096

// ---- scratch (no allocation allowed) ----
__device__ float g_q[(size_t)BB * HH * SSEQ * DH];    // [B,H,S,D]
__device__ float g_k[(size_t)BB * HH * SSEQ * DH];
__device__ float g_v[(size_t)BB * HH * SSEQ * DH];
__device__ float g_ctx[(size_t)BB * SSEQ * EMB];      // [B,S,E]

// ============================================================================
// GEMM: C = A @ W^T + bias.  A [M,K] row-major, W [N,K] row-major.
// SPLIT=1: write C into [B,H,S,D] head-split layout. SPLIT=0: [M,N] row-major.
// 128x128 block tile, BK=8, 256 threads, 8x8 microtile (cols interleaved by 16
// for conflict-free scalar B reads), register-prefetch double buffering.
// ============================================================================
template <int SPLIT>
__global__ __launch_bounds__(256, 2)
void gemm_nt_bias(const float* __restrict__ A, const float* __restrict__ W,
                  const float* __restrict__ bias, float* __restrict__ C,
                  int M, int N, int K)
{
    __shared__ float As[8][132];
    __shared__ float Bs[8][132];

    const int tid = threadIdx.x;
    const int bm = blockIdx.y << 7;
    const int bn = blockIdx.x << 7;
    const int tx = tid & 15;        // col group 0..15
    const int ty = tid >> 4;        // row group 0..15
    const int lr = tid >> 1;        // load row 0..127
    const int lk = (tid & 1) << 2;  // load k offset 0 or 4

    const float* Ap = A + (size_t)(bm + lr) * K + lk;
    const float* Wp = W + (size_t)(bn + lr) * K + lk;

    float4 pa = *(const float4*)Ap;
    float4 pb = *(const float4*)Wp;

    float acc[8][8];
#pragma unroll
    for (int i = 0; i < 8; i++)
#pragma unroll
        for (int j = 0; j < 8; j++) acc[i][j] = 0.f;

    const int nk = K >> 3;
    for (int ks = 0; ks < nk; ks++) {
        As[lk + 0][lr] = pa.x; As[lk + 1][lr] = pa.y;
        As[lk + 2][lr] = pa.z; As[lk + 3][lr] = pa.w;
        Bs[lk + 0][lr] = pb.x; Bs[lk + 1][lr] = pb.y;
        Bs[lk + 2][lr] = pb.z; Bs[lk + 3][lr] = pb.w;
        __syncthreads();
        if (ks + 1 < nk) {
            pa = *(const float4*)(Ap + (size_t)(ks + 1) * 8);
            pb = *(const float4*)(Wp + (size_t)(ks + 1) * 8);
        }
#pragma unroll
        for (int k = 0; k < 8; k++) {
            float4 a0 = *(const float4*)&As[k][ty * 8];
            float4 a1 = *(const float4*)&As[k][ty * 8 + 4];
            float a[8] = {a0.x, a0.y, a0.z, a0.w, a1.x, a1.y, a1.z, a1.w};
            float b[8];
#pragma unroll
            for (int j = 0; j < 8; j++) b[j] = Bs[k][tx + j * 16];
#pragma unroll
            for (int i = 0; i < 8; i++)
#pragma unroll
                for (int j = 0; j < 8; j++)
                    acc[i][j] += a[i] * b[j];
        }
        __syncthreads();
    }

#pragma unroll
    for (int i = 0; i < 8; i++) {
        const int m = bm + ty * 8 + i;
        const int bidx = m >> 11;       // m / SSEQ
        const int srow = m & (SSEQ - 1);
#pragma unroll
        for (int j = 0; j < 8; j++) {
            const int n = bn + tx + j * 16;
            const float v = acc[i][j] + bias[n];
            if (SPLIT) {
                const int h = n >> 6;
                const int d = n & (DH - 1);
                C[(((size_t)bidx * HH + h) * SSEQ + srow) * DH + d] = v;
            } else {
                C[(size_t)m * N + n] = v;
            }
        }
    }
}

// ============================================================================
// Flash attention with QBNN score correction.
// score(i,j) = Q[i]·K[j]/8 + lam * (tanh(Q[i])@J[h]) · tanh(K[j])
// Folded: Q' = [Q*0.125 | lam*(tanh(Q)@J)] (128-wide), K' = [K | tanh(K)].
// BQ=128 query rows per block, BK=64 keys per tile. 256 threads, 4x8 microtile
// (rows ty*4.., cols tx + j*8 interleaved => conflict-free smem access).
// ============================================================================
__global__ __launch_bounds__(256, 1)
void flash_qbnn(const float* __restrict__ Qg, const float* __restrict__ Kg,
                const float* __restrict__ Vg, const float* __restrict__ Jg,
                const float* __restrict__ lam_ptr, float* __restrict__ ctx)
{
    extern __shared__ float sm[];
    float* Qs = sm;                    // 128 x 132 (cols 0..63 Q*0.125, 64..127 lam*QJ)
    float* Ks = Qs + 128 * 132;        // 64 x 132  (cols 0..63 K, 64..127 tanh(K))
    float* Vs = Ks + 64 * 132;         // 64 x 68   (prologue: J[h]; mainloop: V tile)
    float* Ps = Vs + 64 * 68;          // 128 x 68  (prologue: tanh(Q); mainloop: P)

    const int tid = threadIdx.x;
    const int tx = tid & 7;            // 0..7
    const int ty = tid >> 3;           // 0..31
    const int qt = blockIdx.x;         // query tile 0..15
    const int bh = blockIdx.y;         // 0..31 (= b*H + h)
    const int h = bh & (HH - 1);
    const float lam = *lam_ptr;

    const float* Qb = Qg + ((size_t)bh * SSEQ + (size_t)qt * 128) * DH;
    const float* Kb = Kg + (size_t)bh * SSEQ * DH;
    const float* Vb = Vg + (size_t)bh * SSEQ * DH;

    // --- prologue: load Q tile (raw -> Qs[:,0:64], tanh -> Ps) ---
#pragma unroll
    for (int it = 0; it < 8; it++) {
        int idx = tid + it * 256;      // 0..2047 float4s
        int r = idx >> 4;
        int c = (idx & 15) << 2;
        float4 v = *(const float4*)(Qb + r * DH + c);
        Qs[r * 132 + c + 0] = v.x; Qs[r * 132 + c + 1] = v.y;
        Qs[r * 132 + c + 2] = v.z; Qs[r * 132 + c + 3] = v.w;
        Ps[r * 68 + c + 0] = tanhf(v.x); Ps[r * 68 + c + 1] = tanhf(v.y);
        Ps[r * 68 + c + 2] = tanhf(v.z); Ps[r * 68 + c + 3] = tanhf(v.w);
    }
    // load J[h] into Vs (stride 68)
    const float* Jb = Jg + (size_t)h * DH * DH;
#pragma unroll
    for (int it = 0; it < 4; it++) {
        int idx = tid + it * 256;      // 0..1023
        int r = idx >> 4;
        int c = (idx & 15) << 2;
        float4 v = *(const float4*)(Jb + r * DH + c);
        Vs[r * 68 + c + 0] = v.x; Vs[r * 68 + c + 1] = v.y;
        Vs[r * 68 + c + 2] = v.z; Vs[r * 68 + c + 3] = v.w;
    }
    __syncthreads();

    // --- QJ = tanh(Q) @ J; Qs[:,64+c] = lam*QJ; Qs[:,c] *= 0.125 ---
    {
        float acc[4][8];
#pragma unroll
        for (int i = 0; i < 4; i++)
#pragma unroll
            for (int j = 0; j < 8; j++) acc[i][j] = 0.f;
#pragma unroll 4
        for (int d0 = 0; d0 < 64; d0 += 4) {
            float a[4][4];
#pragma unroll
            for (int i = 0; i < 4; i++) {
                float4 t = *(const float4*)&Ps[(ty * 4 + i) * 68 + d0];
                a[i][0] = t.x; a[i][1] = t.y; a[i][2] = t.z; a[i][3] = t.w;
            }
#pragma unroll
            for (int dd = 0; dd < 4; dd++) {
                float b[8];
#pragma unroll
                for (int j = 0; j < 8; j++)
                    b[j] = Vs[(d0 + dd) * 68 + tx + j * 8];
#pragma unroll
                for (int i = 0; i < 4; i++)
#pragma unroll
                    for (int j = 0; j < 8; j++)
                        acc[i][j] += a[i][dd] * b[j];
            }
        }
#pragma unroll
        for (int i = 0; i < 4; i++) {
            int r = ty * 4 + i;
#pragma unroll
            for (int j = 0; j < 8; j++) {
                int c = tx + j * 8;
                Qs[r * 132 + 64 + c] = lam * acc[i][j];
                Qs[r * 132 + c] *= 0.125f;
            }
        }
    }
    __syncthreads();

    float mrow[4], lrow[4], o[4][8];
#pragma unroll
    for (int i = 0; i < 4; i++) { mrow[i] = -1e30f; lrow[i] = 0.f; }
#pragma unroll
    for (int i = 0; i < 4; i++)
#pragma unroll
        for (int j = 0; j < 8; j++) o[i][j] = 0.f;

    for (int kt = 0; kt < SSEQ / 64; kt++) {
        const float* Kt = Kb + (size_t)kt * 64 * DH;
        const float* Vt = Vb + (size_t)kt * 64 * DH;
#pragma unroll
        for (int it = 0; it < 4; it++) {
            int idx = tid + it * 256;  // 0..1023 float4s
            int r = idx >> 4;
            int c = (idx & 15) << 2;
            float4 kv = *(const float4*)(Kt + r * DH + c);
            Ks[r * 132 + c + 0] = kv.x; Ks[r * 132 + c + 1] = kv.y;
            Ks[r * 132 + c + 2] = kv.z; Ks[r * 132 + c + 3] = kv.w;
            Ks[r * 132 + 64 + c + 0] = tanhf(kv.x);
            Ks[r * 132 + 64 + c + 1] = tanhf(kv.y);
            Ks[r * 132 + 64 + c + 2] = tanhf(kv.z);
            Ks[r * 132 + 64 + c + 3] = tanhf(kv.w);
            float4 vv = *(const float4*)(Vt + r * DH + c);
            Vs[r * 68 + c + 0] = vv.x; Vs[r * 68 + c + 1] = vv.y;
            Vs[r * 68 + c + 2] = vv.z; Vs[r * 68 + c + 3] = vv.w;
        }
        __syncthreads();

        // ---- S = Q' @ K'^T (depth 128) ----
        float sc[4][8];
#pragma unroll
        for (int i = 0; i < 4; i++)
#pragma unroll
            for (int j = 0; j < 8; j++) sc[i][j] = 0.f;
#pragma unroll 4
        for (int kk = 0; kk < 128; kk += 4) {
            float a[4][4];
#pragma unroll
            for (int i = 0; i < 4; i++) {
                float4 t = *(const float4*)&Qs[(ty * 4 + i) * 132 + kk];
                a[i][0] = t.x; a[i][1] = t.y; a[i][2] = t.z; a[i][3] = t.w;
            }
            float4 bv[8];
#pragma unroll
            for (int j = 0; j < 8; j++)
                bv[j] = *(const float4*)&Ks[(tx + j * 8) * 132 + kk];
#pragma unroll
            for (int i = 0; i < 4; i++)
#pragma unroll
                for (int j = 0; j < 8; j++) {
                    sc[i][j] += a[i][0] * bv[j].x;
                    sc[i][j] += a[i][1] * bv[j].y;
                    sc[i][j] += a[i][2] * bv[j].z;
                    sc[i][j] += a[i][3] * bv[j].w;
                }
        }

        // ---- online softmax (row groups of 8 lanes: tx = lane&7) ----
#pragma unroll
        for (int i = 0; i < 4; i++) {
            float rm = sc[i][0];
#pragma unroll
            for (int j = 1; j < 8; j++) rm = fmaxf(rm, sc[i][j]);
            rm = fmaxf(rm, __shfl_xor_sync(0xffffffffu, rm, 1));
            rm = fmaxf(rm, __shfl_xor_sync(0xffffffffu, rm, 2));
            rm = fmaxf(rm, __shfl_xor_sync(0xffffffffu, rm, 4));
            const float mnew = fmaxf(mrow[i], rm);
            const float alpha = __expf(mrow[i] - mnew);
            mrow[i] = mnew;
            float rs = 0.f;
#pragma unroll
            for (int j = 0; j < 8; j++) {
                float p = __expf(sc[i][j] - mnew);
                sc[i][j] = p;
                rs += p;
            }
            rs += __shfl_xor_sync(0xffffffffu, rs, 1);
            rs += __shfl_xor_sync(0xffffffffu, rs, 2);
            rs += __shfl_xor_sync(0xffffffffu, rs, 4);
            lrow[i] = lrow[i] * alpha + rs;
#pragma unroll
            for (int j = 0; j < 8; j++) o[i][j] *= alpha;
#pragma unroll
            for (int j = 0; j < 8; j++)
                Ps[(ty * 4 + i) * 68 + tx + j * 8] = sc[i][j];
        }
        __syncthreads();

        // ---- O += P @ V ----
#pragma unroll 4
        for (int kk = 0; kk < 64; kk += 4) {
            float a[4][4];
#pragma unroll
            for (int i = 0; i < 4; i++) {
                float4 t = *(const float4*)&Ps[(ty * 4 + i) * 68 + kk];
                a[i][0] = t.x; a[i][1] = t.y; a[i][2] = t.z; a[i][3] = t.w;
            }
#pragma unroll
            for (int dd = 0; dd < 4; dd++) {
                float b[8];
#pragma unroll
                for (int j = 0; j < 8; j++)
                    b[j] = Vs[(kk + dd) * 68 + tx + j * 8];
#pragma unroll
                for (int i = 0; i < 4; i++)
#pragma unroll
                    for (int j = 0; j < 8; j++)
                        o[i][j] += a[i][dd] * b[j];
            }
        }
        __syncthreads();
    }

    // ---- write ctx[b, s, h*64 + c] = O / l ----
    const int b = bh >> 4;
#pragma unroll
    for (int i = 0; i < 4; i++) {
        const float inv = 1.f / lrow[i];
        const int srow = qt * 128 + ty * 4 + i;
        float* dst = ctx + ((size_t)b * SSEQ + srow) * EMB + h * DH;
#pragma unroll
        for (int j = 0; j < 8; j++)
            dst[tx + j * 8] = o[i][j] * inv;
    }
}

// ============================================================================
extern "C" void kernel_launch(void* const* d_in, const int* in_sizes, int n_in,
                              void* d_out, int out_size)
{
    const float* x   = (const float*)d_in[0];
    const float* Wq  = (const float*)d_in[1];
    const float* bq  = (const float*)d_in[2];
    const float* Wk  = (const float*)d_in[3];
    const float* bk  = (const float*)d_in[4];
    const float* Wv  = (const float*)d_in[5];
    const float* bv  = (const float*)d_in[6];
    const float* Wo  = (const float*)d_in[7];
    const float* bo  = (const float*)d_in[8];
    const float* J   = (const float*)d_in[9];
    const float* lam = (const float*)d_in[10];
    float* out = (float*)d_out;
    (void)in_sizes; (void)n_in; (void)out_size;

    float *q, *k, *v, *ctx;
    cudaGetSymbolAddress((void**)&q, g_q);
    cudaGetSymbolAddress((void**)&k, g_k);
    cudaGetSymbolAddress((void**)&v, g_v);
    cudaGetSymbolAddress((void**)&ctx, g_ctx);

    dim3 ggrid(EMB / 128, MTOT / 128);
    gemm_nt_bias<1><<<ggrid, 256>>>(x, Wq, bq, q, MTOT, EMB, EMB);
    gemm_nt_bias<1><<<ggrid, 256>>>(x, Wk, bk, k, MTOT, EMB, EMB);
    gemm_nt_bias<1><<<ggrid, 256>>>(x, Wv, bv, v, MTOT, EMB, EMB);

    const size_t smem = (128 * 132 + 64 * 132 + 64 * 68 + 128 * 68) * sizeof(float);
    cudaFuncSetAttribute(flash_qbnn, cudaFuncAttributeMaxDynamicSharedMemorySize, (int)smem);
    flash_qbnn<<<dim3(SSEQ / 128, BB * HH), 256, smem>>>(q, k, v, J, lam, ctx);

    gemm_nt_bias<0><<<ggrid, 256>>>(ctx, Wo, bo, out, MTOT, EMB, EMB);
}

// round 14
// speedup vs baseline: 2.7953x; 2.7953x over previous
#include <cuda_runtime.h>
#include <cuda_bf16.h>
#include <cstdint>
#include <math.h>

#define BB   2
#define HH   16
#define SSEQ 2048
#define DH   64
#define EMB  1024
#define MTOT (BB * SSEQ)   // 4096

// ---- scratch (no allocation allowed) ----
__device__ float g_q[(size_t)BB * HH * SSEQ * DH];            // [B,H,S,D] fp32
__device__ float g_ctx[(size_t)BB * SSEQ * EMB];              // [B,S,E]  fp32
// K' = [K | tanh(K)] bf16 hi/lo split, [bh][s][128]
__device__ __nv_bfloat16 g_kx_h[(size_t)BB * HH * SSEQ * 128];
__device__ __nv_bfloat16 g_kx_l[(size_t)BB * HH * SSEQ * 128];
// V bf16 hi/lo split, [bh][s][64]
__device__ __nv_bfloat16 g_vx_h[(size_t)BB * HH * SSEQ * 64];
__device__ __nv_bfloat16 g_vx_l[(size_t)BB * HH * SSEQ * 64];

// ============================================================================
// helpers
// ============================================================================
__device__ __forceinline__ uint32_t smem_u32(const void* p) {
    uint32_t a;
    asm("{ .reg .u64 t; cvta.to.shared.u64 t, %1; cvt.u32.u64 %0, t; }" : "=r"(a) : "l"(p));
    return a;
}
__device__ __forceinline__ void ldsm4(uint32_t* r, uint32_t addr) {
    asm volatile("ldmatrix.sync.aligned.m8n8.x4.shared.b16 {%0,%1,%2,%3}, [%4];"
        : "=r"(r[0]), "=r"(r[1]), "=r"(r[2]), "=r"(r[3]) : "r"(addr));
}
__device__ __forceinline__ void ldsm4t(uint32_t* r, uint32_t addr) {
    asm volatile("ldmatrix.sync.aligned.m8n8.x4.trans.shared.b16 {%0,%1,%2,%3}, [%4];"
        : "=r"(r[0]), "=r"(r[1]), "=r"(r[2]), "=r"(r[3]) : "r"(addr));
}
// D += A(bf16 m16k16) * B(bf16 k16n8), fp32 accum
__device__ __forceinline__ void mma_bf16(float* d, const uint32_t* a, uint32_t b0, uint32_t b1) {
    asm volatile("mma.sync.aligned.m16n8k16.row.col.f32.bf16.bf16.f32 "
        "{%0,%1,%2,%3}, {%4,%5,%6,%7}, {%8,%9}, {%0,%1,%2,%3};"
        : "+f"(d[0]), "+f"(d[1]), "+f"(d[2]), "+f"(d[3])
        : "r"(a[0]), "r"(a[1]), "r"(a[2]), "r"(a[3]), "r"(b0), "r"(b1));
}
// pack two f32 -> bf16x2 (lo in low half)
__device__ __forceinline__ uint32_t packbf(float lo, float hi) {
    uint32_t r;
    asm("cvt.rn.bf16x2.f32 %0, %1, %2;" : "=r"(r) : "f"(hi), "f"(lo));
    return r;
}
__device__ __forceinline__ float bflo(uint32_t u) { return __uint_as_float(u << 16); }
__device__ __forceinline__ float bfhi(uint32_t u) { return __uint_as_float(u & 0xffff0000u); }

// float4 -> bf16 hi pair, lo pair (residual split)
__device__ __forceinline__ void split4(float4 v, uint32_t& h0, uint32_t& h1,
                                       uint32_t& l0, uint32_t& l1) {
    h0 = packbf(v.x, v.y);
    h1 = packbf(v.z, v.w);
    l0 = packbf(v.x - bflo(h0), v.y - bfhi(h0));
    l1 = packbf(v.z - bflo(h1), v.w - bfhi(h1));
}

__device__ __forceinline__ void cpa16(uint32_t dst, const void* src) {
    asm volatile("cp.async.cg.shared.global [%0], [%1], 16;" :: "r"(dst), "l"(src));
}
#define CP_COMMIT() asm volatile("cp.async.commit_group;" ::: "memory")
#define CP_WAIT1()  asm volatile("cp.async.wait_group 1;" ::: "memory")
#define CP_WAIT0()  asm volatile("cp.async.wait_group 0;" ::: "memory")

// ============================================================================
// HMMA bf16-split GEMM: C = A @ W^T + bias.
// A [4096,1024] fp32 row-major, W [1024,1024] fp32 row-major (K contiguous).
// CTA tile 128x128, K-chunk 32, 8 warps (2M x 4N), warp tile 64x32.
// 3 products per k16: AhBh + AhBl + AlBh.
// OPROJ=0: fused QKV, blockIdx.z = 0(Q) 1(K -> kx ext +tanh) 2(V -> vx ext).
// OPROJ=1: plain fp32 output (O projection).
// smem/stage: Ah,Al,Bh,Bl each 128 rows x 40 halves (80B stride; 80*i mod 128
// distinct for i=0..7 -> conflict-free ldmatrix). 40960B/stage, 2 stages.
// ============================================================================
template <int OPROJ>
__global__ __launch_bounds__(256, 1)
void gemm_mma(const float* __restrict__ A,
              const float* __restrict__ W0, const float* __restrict__ b0p,
              const float* __restrict__ W1, const float* __restrict__ b1p,
              const float* __restrict__ W2, const float* __restrict__ b2p,
              float* __restrict__ Oout)
{
    extern __shared__ __align__(16) char dyn[];
    const int tid = threadIdx.x;
    const int lane = tid & 31;
    const int wid = tid >> 5;
    const int bm = blockIdx.y << 7;
    const int bn = blockIdx.x << 7;
    const int mode = OPROJ ? 3 : (int)blockIdx.z;

    const float* W    = (OPROJ || mode == 0) ? W0 : (mode == 1) ? W1 : W2;
    const float* bias = (OPROJ || mode == 0) ? b0p : (mode == 1) ? b1p : b2p;

    const int wm = (wid >> 2) * 64;
    const int wn = (wid & 3) * 32;

    const float* Abase = A + (size_t)bm * EMB;
    const float* Wbase = W + (size_t)bn * EMB;
    const uint32_t sbase = smem_u32(dyn);

    float acc[4][4][4];
#pragma unroll
    for (int i = 0; i < 4; i++)
#pragma unroll
        for (int j = 0; j < 4; j++)
#pragma unroll
            for (int t = 0; t < 4; t++) acc[i][j][t] = 0.f;

    float4 ra[4], rb[4];
    // load chunk 0
#pragma unroll
    for (int it = 0; it < 4; it++) {
        int idx = tid + it * 256;
        int r = idx >> 3, g = idx & 7;
        ra[it] = *(const float4*)(Abase + (size_t)r * EMB + g * 4);
        rb[it] = *(const float4*)(Wbase + (size_t)r * EMB + g * 4);
    }

    for (int c = 0; c < 32; c++) {
        char* st = dyn + (size_t)(c & 1) * 40960;
#pragma unroll
        for (int it = 0; it < 4; it++) {
            int idx = tid + it * 256;
            int r = idx >> 3, g = idx & 7;
            uint32_t h0, h1, l0, l1;
            split4(ra[it], h0, h1, l0, l1);
            *(uint2*)(st +         r * 80 + g * 8) = make_uint2(h0, h1);
            *(uint2*)(st + 10240 + r * 80 + g * 8) = make_uint2(l0, l1);
            split4(rb[it], h0, h1, l0, l1);
            *(uint2*)(st + 20480 + r * 80 + g * 8) = make_uint2(h0, h1);
            *(uint2*)(st + 30720 + r * 80 + g * 8) = make_uint2(l0, l1);
        }
        __syncthreads();
        if (c + 1 < 32) {
            const int kc = (c + 1) * 32;
#pragma unroll
            for (int it = 0; it < 4; it++) {
                int idx = tid + it * 256;
                int r = idx >> 3, g = idx & 7;
                ra[it] = *(const float4*)(Abase + (size_t)r * EMB + kc + g * 4);
                rb[it] = *(const float4*)(Wbase + (size_t)r * EMB + kc + g * 4);
            }
        }
        const uint32_t sb = sbase + (uint32_t)(c & 1) * 40960u;
#pragma unroll
        for (int ks = 0; ks < 2; ks++) {
            uint32_t ah[4][4], al[4][4];
#pragma unroll
            for (int mt = 0; mt < 4; mt++) {
                uint32_t ad = sb + (uint32_t)((wm + mt * 16 + (lane & 15)) * 80
                                              + (ks * 16 + (lane >> 4) * 8) * 2);
                ldsm4(ah[mt], ad);
                ldsm4(al[mt], ad + 10240);
            }
            uint32_t bh[4][2], bl[4][2];
#pragma unroll
            for (int u = 0; u < 2; u++) {
                uint32_t bd = sb + 20480u
                    + (uint32_t)((wn + u * 16 + (lane & 7) + ((lane >> 4) & 1) * 8) * 80
                                 + (ks * 16 + ((lane >> 3) & 1) * 8) * 2);
                uint32_t r4[4];
                ldsm4(r4, bd);
                bh[2 * u][0] = r4[0]; bh[2 * u][1] = r4[1];
                bh[2 * u + 1][0] = r4[2]; bh[2 * u + 1][1] = r4[3];
                ldsm4(r4, bd + 10240);
                bl[2 * u][0] = r4[0]; bl[2 * u][1] = r4[1];
                bl[2 * u + 1][0] = r4[2]; bl[2 * u + 1][1] = r4[3];
            }
#pragma unroll
            for (int mt = 0; mt < 4; mt++)
#pragma unroll
                for (int nt = 0; nt < 4; nt++) {
                    mma_bf16(acc[mt][nt], ah[mt], bh[nt][0], bh[nt][1]);
                    mma_bf16(acc[mt][nt], ah[mt], bl[nt][0], bl[nt][1]);
                    mma_bf16(acc[mt][nt], al[mt], bh[nt][0], bh[nt][1]);
                }
        }
        __syncthreads();
    }

    // ---- epilogue ----
#pragma unroll
    for (int mt = 0; mt < 4; mt++)
#pragma unroll
        for (int nt = 0; nt < 4; nt++)
#pragma unroll
            for (int half = 0; half < 2; half++) {
                const int m = bm + wm + mt * 16 + (lane >> 2) + half * 8;
                const int n = bn + wn + nt * 8 + (lane & 3) * 2;
                float v0 = acc[mt][nt][half * 2 + 0] + bias[n];
                float v1 = acc[mt][nt][half * 2 + 1] + bias[n + 1];
                if (OPROJ) {
                    *(float2*)(Oout + (size_t)m * EMB + n) = make_float2(v0, v1);
                } else if (mode == 0) {
                    const int hh = n >> 6, d = n & 63;
                    const int bq = m >> 11, s = m & 2047;
                    *(float2*)(&g_q[(((size_t)bq * HH + hh) * SSEQ + s) * DH + d]) =
                        make_float2(v0, v1);
                } else {
                    const int bhd = (m >> 11) * HH + (n >> 6);
                    const int d = n & 63, s = m & 2047;
                    uint32_t h0 = packbf(v0, v1);
                    uint32_t l0 = packbf(v0 - bflo(h0), v1 - bfhi(h0));
                    if (mode == 1) {
                        const size_t base = ((size_t)bhd * SSEQ + s) * 128 + d;
                        *(uint32_t*)&g_kx_h[base] = h0;
                        *(uint32_t*)&g_kx_l[base] = l0;
                        float t0 = tanhf(v0), t1 = tanhf(v1);
                        uint32_t th = packbf(t0, t1);
                        uint32_t tl = packbf(t0 - bflo(th), t1 - bfhi(th));
                        *(uint32_t*)&g_kx_h[base + 64] = th;
                        *(uint32_t*)&g_kx_l[base + 64] = tl;
                    } else {
                        const size_t base = ((size_t)bhd * SSEQ + s) * 64 + d;
                        *(uint32_t*)&g_vx_h[base] = h0;
                        *(uint32_t*)&g_vx_l[base] = l0;
                    }
                }
            }
}

// ============================================================================
// Flash attention (HMMA): score = Q'(128-deep) . K'^T, online softmax per
// 16-row warp (stats in registers, P repacked accum->A-frag, no smem P).
// Q' = [Q*0.125 | lam*(tanh(Q)@J)] built in prologue (fp32), split hi/lo bf16.
// smem (bytes):
//   [0,      34816)  Qh  128 x 136 halves (272B stride)   | prologue: tanhQ f32
//   [34816,  69632)  Ql                                    | prologue: J f32
//   [69632, 176128)  2 stages x { Kh 17408 | Kl 17408 | Vh 9216 | Vl 9216 }
//                                                          | prologue: QS f32 128x132
// ============================================================================
#define F_QH   0
#define F_QL   34816
#define F_STG  69632
#define F_SSZ  53248
#define F_KL   17408
#define F_VH   34816
#define F_VL   44032
#define F_TOT  176128

__global__ __launch_bounds__(256, 1)
void flash_mma(const float* __restrict__ Jg, const float* __restrict__ lam_ptr,
               float* __restrict__ ctx)
{
    extern __shared__ __align__(16) char dyn[];
    const int tid = threadIdx.x;
    const int lane = tid & 31;
    const int w = tid >> 5;          // warp 0..7 -> q rows w*16..
    const int qt = blockIdx.x;       // 0..15
    const int bh = blockIdx.y;       // 0..31
    const int h = bh & (HH - 1);
    const int b = bh >> 4;
    const float lam = *lam_ptr;
    const uint32_t sb0 = smem_u32(dyn);

    float* QS = (float*)(dyn + F_STG);   // 128 x 132 fp32
    float* TQ = (float*)(dyn);           // 128 x 68  fp32
    float* JS = (float*)(dyn + 34816);   // 64 x 68   fp32

    // ---- prologue: Q raw + tanh(Q), J ----
    const float* Qb = g_q + ((size_t)bh * SSEQ + (size_t)qt * 128) * DH;
#pragma unroll
    for (int it = 0; it < 8; it++) {
        int idx = tid + it * 256;
        int r = idx >> 4, c = (idx & 15) << 2;
        float4 v = *(const float4*)(Qb + r * DH + c);
        QS[r * 132 + c + 0] = v.x; QS[r * 132 + c + 1] = v.y;
        QS[r * 132 + c + 2] = v.z; QS[r * 132 + c + 3] = v.w;
        TQ[r * 68 + c + 0] = tanhf(v.x); TQ[r * 68 + c + 1] = tanhf(v.y);
        TQ[r * 68 + c + 2] = tanhf(v.z); TQ[r * 68 + c + 3] = tanhf(v.w);
    }
    const float* Jb = Jg + (size_t)h * DH * DH;
#pragma unroll
    for (int it = 0; it < 4; it++) {
        int idx = tid + it * 256;
        int r = idx >> 4, c = (idx & 15) << 2;
        float4 v = *(const float4*)(Jb + r * DH + c);
        JS[r * 68 + c + 0] = v.x; JS[r * 68 + c + 1] = v.y;
        JS[r * 68 + c + 2] = v.z; JS[r * 68 + c + 3] = v.w;
    }
    __syncthreads();

    // ---- QJ = tanh(Q) @ J (scalar fp32, tiny) ----
    {
        const int tx = tid & 7, ty = tid >> 3;
        float a2[4][8];
#pragma unroll
        for (int i = 0; i < 4; i++)
#pragma unroll
            for (int j = 0; j < 8; j++) a2[i][j] = 0.f;
#pragma unroll 4
        for (int d0 = 0; d0 < 64; d0 += 4) {
            float a[4][4];
#pragma unroll
            for (int i = 0; i < 4; i++) {
                float4 t = *(const float4*)&TQ[(ty * 4 + i) * 68 + d0];
                a[i][0] = t.x; a[i][1] = t.y; a[i][2] = t.z; a[i][3] = t.w;
            }
#pragma unroll
            for (int dd = 0; dd < 4; dd++) {
                float bb[8];
#pragma unroll
                for (int j = 0; j < 8; j++) bb[j] = JS[(d0 + dd) * 68 + tx + j * 8];
#pragma unroll
                for (int i = 0; i < 4; i++)
#pragma unroll
                    for (int j = 0; j < 8; j++) a2[i][j] += a[i][dd] * bb[j];
            }
        }
#pragma unroll
        for (int i = 0; i < 4; i++) {
            int r = ty * 4 + i;
#pragma unroll
            for (int j = 0; j < 8; j++) {
                int c = tx + j * 8;
                QS[r * 132 + 64 + c] = lam * a2[i][j];
                QS[r * 132 + c] *= 0.125f;
            }
        }
    }
    __syncthreads();

    // ---- convert QS fp32 -> Qh/Ql bf16 tiles (overwrites TQ/JS) ----
#pragma unroll
    for (int it = 0; it < 16; it++) {
        int idx = tid + it * 256;
        int r = idx >> 5, g = idx & 31;
        float4 v = *(const float4*)&QS[r * 132 + g * 4];
        uint32_t h0, h1, l0, l1;
        split4(v, h0, h1, l0, l1);
        *(uint2*)(dyn + F_QH + r * 272 + g * 8) = make_uint2(h0, h1);
        *(uint2*)(dyn + F_QL + r * 272 + g * 8) = make_uint2(l0, l1);
    }
    __syncthreads();

    // ---- pipeline gmem pointers ----
    const __nv_bfloat16* KHg = g_kx_h + (size_t)bh * SSEQ * 128;
    const __nv_bfloat16* KLg = g_kx_l + (size_t)bh * SSEQ * 128;
    const __nv_bfloat16* VHg = g_vx_h + (size_t)bh * SSEQ * 64;
    const __nv_bfloat16* VLg = g_vx_l + (size_t)bh * SSEQ * 64;

    auto prefetch = [&](int kt) {
        uint32_t d = sb0 + F_STG + (uint32_t)(kt & 1) * F_SSZ;
        const int s0 = kt * 64;
#pragma unroll
        for (int it = 0; it < 4; it++) {
            int idx = tid + it * 256;
            int r = idx >> 4, g = idx & 15;
            cpa16(d +        r * 272 + g * 16, KHg + (size_t)(s0 + r) * 128 + g * 8);
            cpa16(d + F_KL + r * 272 + g * 16, KLg + (size_t)(s0 + r) * 128 + g * 8);
        }
#pragma unroll
        for (int it = 0; it < 2; it++) {
            int idx = tid + it * 256;
            int r = idx >> 3, g = idx & 7;
            cpa16(d + F_VH + r * 144 + g * 16, VHg + (size_t)(s0 + r) * 64 + g * 8);
            cpa16(d + F_VL + r * 144 + g * 16, VLg + (size_t)(s0 + r) * 64 + g * 8);
        }
    };

    prefetch(0);
    CP_COMMIT();

    // ---- preload Q fragments (per warp: rows w*16..w*16+15, k 0..127) ----
    uint32_t qh[8][4], ql[8][4];
#pragma unroll
    for (int ks = 0; ks < 8; ks++) {
        uint32_t ad = sb0 + F_QH + (uint32_t)((w * 16 + (lane & 15)) * 272
                                              + (ks * 16 + (lane >> 4) * 8) * 2);
        ldsm4(qh[ks], ad);
        ldsm4(ql[ks], ad + F_QL);
    }

    float o[8][4];
#pragma unroll
    for (int i = 0; i < 8; i++)
#pragma unroll
        for (int t = 0; t < 4; t++) o[i][t] = 0.f;
    float mrow[2] = { -1e30f, -1e30f };
    float lsum[2] = { 0.f, 0.f };

    for (int kt = 0; kt < SSEQ / 64; kt++) {
        if (kt + 1 < SSEQ / 64) {
            prefetch(kt + 1);
            CP_COMMIT();
            CP_WAIT1();
        } else {
            CP_WAIT0();
        }
        __syncthreads();

        const uint32_t sb = sb0 + F_STG + (uint32_t)(kt & 1) * F_SSZ;

        // ---- S = Q' . K'^T (3-product split), per warp 16x64 ----
        float s[8][4];
#pragma unroll
        for (int i = 0; i < 8; i++)
#pragma unroll
            for (int t = 0; t < 4; t++) s[i][t] = 0.f;
#pragma unroll
        for (int ks = 0; ks < 8; ks++) {
#pragma unroll
            for (int u = 0; u < 4; u++) {
                uint32_t bd = sb + (uint32_t)((u * 16 + (lane & 7) + ((lane >> 4) & 1) * 8) * 272
                                              + (ks * 16 + ((lane >> 3) & 1) * 8) * 2);
                uint32_t kh4[4], kl4[4];
                ldsm4(kh4, bd);
                ldsm4(kl4, bd + F_KL);
                mma_bf16(s[2 * u],     qh[ks], kh4[0], kh4[1]);
                mma_bf16(s[2 * u],     qh[ks], kl4[0], kl4[1]);
                mma_bf16(s[2 * u],     ql[ks], kh4[0], kh4[1]);
                mma_bf16(s[2 * u + 1], qh[ks], kh4[2], kh4[3]);
                mma_bf16(s[2 * u + 1], qh[ks], kl4[2], kl4[3]);
                mma_bf16(s[2 * u + 1], ql[ks], kh4[2], kh4[3]);
            }
        }

        // ---- online softmax (rows lane>>2 and +8; quad shuffles) ----
#pragma unroll
        for (int rr = 0; rr < 2; rr++) {
            float rm = -1e30f;
#pragma unroll
            for (int nt = 0; nt < 8; nt++) {
                rm = fmaxf(rm, s[nt][rr * 2 + 0]);
                rm = fmaxf(rm, s[nt][rr * 2 + 1]);
            }
            rm = fmaxf(rm, __shfl_xor_sync(0xffffffffu, rm, 1));
            rm = fmaxf(rm, __shfl_xor_sync(0xffffffffu, rm, 2));
            const float mnew = fmaxf(mrow[rr], rm);
            const float alpha = __expf(mrow[rr] - mnew);
            mrow[rr] = mnew;
            float rs = 0.f;
#pragma unroll
            for (int nt = 0; nt < 8; nt++) {
                float p0 = __expf(s[nt][rr * 2 + 0] - mnew);
                float p1 = __expf(s[nt][rr * 2 + 1] - mnew);
                s[nt][rr * 2 + 0] = p0;
                s[nt][rr * 2 + 1] = p1;
                rs += p0 + p1;
            }
            rs += __shfl_xor_sync(0xffffffffu, rs, 1);
            rs += __shfl_xor_sync(0xffffffffu, rs, 2);
            lsum[rr] = lsum[rr] * alpha + rs;
#pragma unroll
            for (int nt = 0; nt < 8; nt++) {
                o[nt][rr * 2 + 0] *= alpha;
                o[nt][rr * 2 + 1] *= alpha;
            }
        }

        // ---- O += P @ V (P repacked from accums, split; V hi/lo) ----
#pragma unroll
        for (int t = 0; t < 4; t++) {
            uint32_t ph[4], pl[4];
            ph[0] = packbf(s[2 * t][0], s[2 * t][1]);
            pl[0] = packbf(s[2 * t][0] - bflo(ph[0]), s[2 * t][1] - bfhi(ph[0]));
            ph[1] = packbf(s[2 * t][2], s[2 * t][3]);
            pl[1] = packbf(s[2 * t][2] - bflo(ph[1]), s[2 * t][3] - bfhi(ph[1]));
            ph[2] = packbf(s[2 * t + 1][0], s[2 * t + 1][1]);
            pl[2] = packbf(s[2 * t + 1][0] - bflo(ph[2]), s[2 * t + 1][1] - bfhi(ph[2]));
            ph[3] = packbf(s[2 * t + 1][2], s[2 * t + 1][3]);
            pl[3] = packbf(s[2 * t + 1][2] - bflo(ph[3]), s[2 * t + 1][3] - bfhi(ph[3]));
#pragma unroll
            for (int u = 0; u < 4; u++) {
                uint32_t vd = sb + F_VH
                    + (uint32_t)((t * 16 + (lane & 7) + ((lane >> 3) & 1) * 8) * 144
                                 + (u * 16 + ((lane >> 4) & 1) * 8) * 2);
                uint32_t vh4[4], vl4[4];
                ldsm4t(vh4, vd);
                ldsm4t(vl4, vd + (F_VL - F_VH));
                mma_bf16(o[2 * u],     ph, vh4[0], vh4[1]);
                mma_bf16(o[2 * u],     ph, vl4[0], vl4[1]);
                mma_bf16(o[2 * u],     pl, vh4[0], vh4[1]);
                mma_bf16(o[2 * u + 1], ph, vh4[2], vh4[3]);
                mma_bf16(o[2 * u + 1], ph, vl4[2], vl4[3]);
                mma_bf16(o[2 * u + 1], pl, vh4[2], vh4[3]);
            }
        }
        __syncthreads();
    }

    // ---- epilogue: ctx[b, s, h*64+d] = O / l ----
    const float inv0 = 1.f / lsum[0];
    const float inv1 = 1.f / lsum[1];
    const int r0 = qt * 128 + w * 16 + (lane >> 2);
#pragma unroll
    for (int nt = 0; nt < 8; nt++) {
        const int d = h * DH + nt * 8 + (lane & 3) * 2;
        *(float2*)(ctx + ((size_t)b * SSEQ + r0) * EMB + d) =
            make_float2(o[nt][0] * inv0, o[nt][1] * inv0);
        *(float2*)(ctx + ((size_t)b * SSEQ + r0 + 8) * EMB + d) =
            make_float2(o[nt][2] * inv1, o[nt][3] * inv1);
    }
}

// ============================================================================
extern "C" void kernel_launch(void* const* d_in, const int* in_sizes, int n_in,
                              void* d_out, int out_size)
{
    const float* x   = (const float*)d_in[0];
    const float* Wq  = (const float*)d_in[1];
    const float* bq  = (const float*)d_in[2];
    const float* Wk  = (const float*)d_in[3];
    const float* bk  = (const float*)d_in[4];
    const float* Wv  = (const float*)d_in[5];
    const float* bv  = (const float*)d_in[6];
    const float* Wo  = (const float*)d_in[7];
    const float* bo  = (const float*)d_in[8];
    const float* J   = (const float*)d_in[9];
    const float* lam = (const float*)d_in[10];
    float* out = (float*)d_out;
    (void)in_sizes; (void)n_in; (void)out_size;

    float* ctx;
    cudaGetSymbolAddress((void**)&ctx, g_ctx);

    const int gsmem = 81920;
    cudaFuncSetAttribute(gemm_mma<0>, cudaFuncAttributeMaxDynamicSharedMemorySize, gsmem);
    cudaFuncSetAttribute(gemm_mma<1>, cudaFuncAttributeMaxDynamicSharedMemorySize, gsmem);
    cudaFuncSetAttribute(flash_mma, cudaFuncAttributeMaxDynamicSharedMemorySize, F_TOT);

    // fused QKV projections; z=0 Q (fp32 split-head), z=1 K (bf16 ext + tanh),
    // z=2 V (bf16 ext)
    gemm_mma<0><<<dim3(EMB / 128, MTOT / 128, 3), 256, gsmem>>>(
        x, Wq, bq, Wk, bk, Wv, bv, nullptr);

    flash_mma<<<dim3(SSEQ / 128, BB * HH), 256, F_TOT>>>(J, lam, ctx);

    // output projection
    gemm_mma<1><<<dim3(EMB / 128, MTOT / 128, 1), 256, gsmem>>>(
        ctx, Wo, bo, nullptr, nullptr, nullptr, nullptr, out);
}